// round 14
// baseline (speedup 1.0000x reference)
#include <cuda_runtime.h>
#include <cstdint>

#define RADIUS 5
#define RS 11
#define EMB 128
#define ROW_B (EMB * 4)            // 512 B per row
#define BB 32
#define LL 512
#define C_BLK 16                   // outputs per block
#define T_BLK (C_BLK + 2*RADIUS)   // 26 window tokens
#define NROWS_S 44                 // rows routed via TMA (outputs 12..15)
#define THREADS 256                // 8 warps
#define RING_OFF 512
#define SMEM_BYTES (RING_OFF + NROWS_S * ROW_B)   // 23040

// For tokens t=12..25, TMA carries run j in [max(0,t-15), min(10,t-12)]
// (exactly the rows consumed by outputs 12..15). Run lengths:
// 1,2,3,4,4,4,4,4,4,4,4,3,2,1  (sum 44). Prefix sums:
__constant__ int PREF_S[14] = {0,1,3,6,10,14,18,22,26,30,34,38,41,43};

__device__ __forceinline__ uint32_t smem_u32(const void* p) {
    uint32_t a;
    asm("{ .reg .u64 t; cvta.to.shared.u64 t, %1; cvt.u32.u64 %0, t; }"
        : "=r"(a) : "l"(p));
    return a;
}
__device__ __forceinline__ void mbar_init(uint32_t a, uint32_t c) {
    asm volatile("mbarrier.init.shared.b64 [%0], %1;" :: "r"(a), "r"(c) : "memory");
}
__device__ __forceinline__ void mbar_expect_tx(uint32_t a, uint32_t bytes) {
    asm volatile("mbarrier.arrive.expect_tx.shared.b64 _, [%0], %1;"
                 :: "r"(a), "r"(bytes) : "memory");
}
__device__ __forceinline__ void mbar_wait(uint32_t a, uint32_t parity) {
    asm volatile(
        "{\n\t.reg .pred P;\n"
        "W_%=:\n\t"
        "mbarrier.try_wait.parity.acquire.cta.shared::cta.b64 P, [%0], %1, 0x989680;\n\t"
        "@P bra D_%=;\n\t"
        "bra W_%=;\n"
        "D_%=:\n\t}"
        :: "r"(a), "r"(parity) : "memory");
}
__device__ __forceinline__ void bulk_g2s(uint32_t dst, const void* src,
                                         uint32_t bytes, uint32_t mbar) {
    asm volatile(
        "cp.async.bulk.shared::cta.global.mbarrier::complete_tx::bytes "
        "[%0], [%1], %2, [%3];"
        :: "r"(dst), "l"(src), "r"(bytes), "r"(mbar) : "memory");
}

// 75/25 dual-engine kernel. Round-13 measured the two paths fully overlapped
// with rates ~8.4 TB/s (LDG/MSHR) and ~3.1 TB/s (cp.async.bulk/TMA); the 1:1
// split made TMA the critical path. Rebalanced: outputs 0..11 of each
// 16-output block go through 6 pure-LDG warps (round-8 inner loop); outputs
// 12..15 consume 44 rows (22.5KB) TMA'd into smem by warp 7. Row sets are
// disjoint, so total traffic is unchanged; the legs run concurrently.
__global__ __launch_bounds__(THREADS, 3) void region_encoder_kernel(
    const int* __restrict__ seq32,
    const float* __restrict__ W,
    const float* __restrict__ U,
    float* __restrict__ out)
{
    extern __shared__ __align__(128) unsigned char smem[];
    const int tid  = threadIdx.x;
    const int wid  = tid >> 5;
    const int lane = tid & 31;
    const int b    = blockIdx.x >> 5;            // batch
    const int L0   = (blockIdx.x & 31) * C_BLK;  // first output of chunk

    const uint32_t mb = smem_u32(smem);
    const uint32_t rg = mb + RING_OFF;
    if (tid == 0) mbar_init(mb, 1);
    __syncthreads();

    // ---- window tokens (lane = t in [0,26)) + dtype detection ----
    // Lanes 26..31 sample odd 32-bit words of seq: int64 layout => all zero;
    // int32 layout (tokens uniform in [0,50000)) => essentially never all zero.
    int det = 0;
    if (lane >= T_BLK) det = seq32[((lane - T_BLK) << 1) + 1];
    const int p    = L0 - RADIUS + lane;
    const bool inb = (lane < T_BLK) && ((unsigned)p < (unsigned)LL);
    const int idx  = b * LL + p;
    int tok = inb ? __ldg(seq32 + idx) : 0;
    const unsigned ball = __ballot_sync(0xffffffffu, det != 0);
    if (ball == 0u) tok = inb ? __ldg(seq32 + (idx << 1)) : 0;  // int64 layout

    if (wid == 7) {
        // ---- producer: fire 14 bulk copies (tokens t=12..25, exact runs) ----
        if (lane == 0) mbar_expect_tx(mb, NROWS_S * ROW_B);
        __syncwarp();
        const int t  = 12 + ((lane < 14) ? lane : 0);
        const int tk = __shfl_sync(0xffffffffu, tok, t);
        if (lane < 14) {
            const int lo = max(0, t - 15);
            const int hi = min(10, t - 12) + 1;
            bulk_g2s(rg + (uint32_t)PREF_S[lane] * ROW_B,
                     (const char*)U + ((size_t)tk * RS + lo) * ROW_B,
                     (uint32_t)(hi - lo) * ROW_B, mb);
        }
    }

    if (wid < 6) {
        // ================ LDG leg: outputs i0 = 2*wid, i0+1 (0..11) ================
        const int i0 = 2 * wid;
        const int c0 = __shfl_sync(0xffffffffu, tok, i0 + RADIUS);
        const int c1 = __shfl_sync(0xffffffffu, tok, i0 + 1 + RADIUS);
        const float4 w0 = __ldg(reinterpret_cast<const float4*>(W + (size_t)c0 * EMB) + lane);
        const float4 w1 = __ldg(reinterpret_cast<const float4*>(W + (size_t)c1 * EMB) + lane);
        const float  m0 = (c0 != 0) ? 1.0f : 0.0f;
        const float  m1 = (c1 != 0) ? 1.0f : 0.0f;

        float4 a0 = make_float4(-INFINITY, -INFINITY, -INFINITY, -INFINITY);
        float4 a1 = a0;

#pragma unroll
        for (int tt = 0; tt < 12; tt++) {           // tokens t = i0 .. i0+11
            const int tk = __shfl_sync(0xffffffffu, tok, i0 + tt);
            const float4* base = reinterpret_cast<const float4*>(U + (size_t)tk * RS * EMB);
            if (tt < RS) {                          // row (t, j=tt) -> out0
                const float4 u = __ldg(base + tt * (EMB / 4) + lane);
                a0.x = fmaxf(a0.x, u.x * w0.x);
                a0.y = fmaxf(a0.y, u.y * w0.y);
                a0.z = fmaxf(a0.z, u.z * w0.z);
                a0.w = fmaxf(a0.w, u.w * w0.w);
            }
            if (tt >= 1) {                          // row (t, j=tt-1) -> out1
                const float4 u = __ldg(base + (tt - 1) * (EMB / 4) + lane);
                a1.x = fmaxf(a1.x, u.x * w1.x);
                a1.y = fmaxf(a1.y, u.y * w1.y);
                a1.z = fmaxf(a1.z, u.z * w1.z);
                a1.w = fmaxf(a1.w, u.w * w1.w);
            }
        }

        float4 h0 = make_float4(a0.x * m0, a0.y * m0, a0.z * m0, a0.w * m0);
        float4 h1 = make_float4(a1.x * m1, a1.y * m1, a1.z * m1, a1.w * m1);
        __stcs(reinterpret_cast<float4*>(out + (size_t)(b * LL + L0 + i0)     * EMB) + lane, h0);
        __stcs(reinterpret_cast<float4*>(out + (size_t)(b * LL + L0 + i0 + 1) * EMB) + lane, h1);
    } else {
        // ================ TMA leg: warps 6,7 -> outputs 12..15 ================
        const int i0 = 12 + 2 * (wid - 6);
        const int c0 = __shfl_sync(0xffffffffu, tok, i0 + RADIUS);
        const int c1 = __shfl_sync(0xffffffffu, tok, i0 + 1 + RADIUS);
        const float4 w0 = __ldg(reinterpret_cast<const float4*>(W + (size_t)c0 * EMB) + lane);
        const float4 w1 = __ldg(reinterpret_cast<const float4*>(W + (size_t)c1 * EMB) + lane);
        const float  m0 = (c0 != 0) ? 1.0f : 0.0f;
        const float  m1 = (c1 != 0) ? 1.0f : 0.0f;

        mbar_wait(mb, 0);

        float4 a0 = make_float4(-INFINITY, -INFINITY, -INFINITY, -INFINITY);
        float4 a1 = a0;
        const float4* rows = reinterpret_cast<const float4*>(smem + RING_OFF);
#pragma unroll
        for (int j = 0; j < RS; j++) {
            const int t0 = i0 + j;                 // token for out0
            const int s0 = PREF_S[t0 - 12] + (j - max(0, t0 - 15));
            const float4 u0 = rows[s0 * (EMB / 4) + lane];
            a0.x = fmaxf(a0.x, u0.x * w0.x);
            a0.y = fmaxf(a0.y, u0.y * w0.y);
            a0.z = fmaxf(a0.z, u0.z * w0.z);
            a0.w = fmaxf(a0.w, u0.w * w0.w);

            const int t1 = i0 + 1 + j;             // token for out1
            const int s1 = PREF_S[t1 - 12] + (j - max(0, t1 - 15));
            const float4 u1 = rows[s1 * (EMB / 4) + lane];
            a1.x = fmaxf(a1.x, u1.x * w1.x);
            a1.y = fmaxf(a1.y, u1.y * w1.y);
            a1.z = fmaxf(a1.z, u1.z * w1.z);
            a1.w = fmaxf(a1.w, u1.w * w1.w);
        }

        float4 h0 = make_float4(a0.x * m0, a0.y * m0, a0.z * m0, a0.w * m0);
        float4 h1 = make_float4(a1.x * m1, a1.y * m1, a1.z * m1, a1.w * m1);
        __stcs(reinterpret_cast<float4*>(out + (size_t)(b * LL + L0 + i0)     * EMB) + lane, h0);
        __stcs(reinterpret_cast<float4*>(out + (size_t)(b * LL + L0 + i0 + 1) * EMB) + lane, h1);
    }
}

extern "C" void kernel_launch(void* const* d_in, const int* in_sizes, int n_in,
                              void* d_out, int out_size) {
    const int*   seq32 = (const int*)d_in[0];
    const float* W     = (const float*)d_in[1];
    const float* U     = (const float*)d_in[2];
    float*       out   = (float*)d_out;

    cudaFuncSetAttribute(region_encoder_kernel,
                         cudaFuncAttributeMaxDynamicSharedMemorySize, SMEM_BYTES);

    const int blocks = BB * (LL / C_BLK);  // 1024
    region_encoder_kernel<<<blocks, THREADS, SMEM_BYTES>>>(seq32, W, U, out);
}

// round 15
// speedup vs baseline: 1.1400x; 1.1400x over previous
#include <cuda_runtime.h>
#include <cstdint>

#define RADIUS 5
#define RS 11            // region size
#define EMB 128
#define BB 32
#define LL 512
#define NPOS (BB * LL)   // 16384
#define C 4              // outputs per warp
#define T (C + 2 * RADIUS) // tokens per warp = 14

// FINAL (round-8 architecture, measured 12.77us = LTS-cap floor).
// Model: warm timed loop moves 108MB of L2-traversing traffic (92MB U rows,
// read exactly once per (position,j); 8MB W; 8MB out) through the
// path-independent LTS cap (~6300 B/cyc ~= 8.4 TB/s at NAT clocks) ->
// floor ~= 12.8us. Verified invariant to occupancy (2x), per-warp MLP (3x),
// L2 policy (evict_last), ALU reduction, cp.async.bulk, and LDG+TMA hybrids.
//
// Token-contiguous formulation: warp owns outputs [L0, L0+4). Token at
// position p contributes row U[t_p*11 + j] to output l = p+5-j, so one
// token's needed rows are a consecutive run inside its contiguous 5632B U
// block (coarse DRAM granularity on the cold pass; read-once by construction).
__global__ __launch_bounds__(256, 4) void region_encoder_kernel(
    const int* __restrict__ seq32,
    const float* __restrict__ W,
    const float* __restrict__ U,
    float* __restrict__ out)
{
    const int warp = blockIdx.x * 8 + (threadIdx.x >> 5);  // 4096 warps
    const int lane = threadIdx.x & 31;

    const int b  = warp >> 7;             // / (LL/C) = /128
    const int L0 = (warp & 127) * C;      // first output of this chunk

    // ---- dtype detection + token loads in flight together ----
    // Lanes 16..31 sample odd 32-bit words of seq: int64 layout => all zero;
    // int32 layout (tokens uniform in [0,50000)) => essentially never all zero.
    int det = 0;
    if (lane >= 16) det = seq32[((lane - 16) << 1) + 1];

    // Lanes 0..13 load tokens p = L0-5+lane (speculative int32 layout).
    const int p    = L0 - RADIUS + lane;
    const bool inb = (lane < T) && ((unsigned)p < (unsigned)LL);
    const int idx  = b * LL + p;
    int tok = inb ? __ldg(seq32 + idx) : 0;

    const unsigned ball = __ballot_sync(0xffffffffu, det != 0);
    if (ball == 0u) {
        tok = inb ? __ldg(seq32 + (idx << 1)) : 0;  // int64 layout (cold path)
    }

    // ---- preload the 4 W rows + masks (early independent LDG.128) ----
    float4 w[C];
    float  msk[C];
#pragma unroll
    for (int i = 0; i < C; i++) {
        const int ct = __shfl_sync(0xffffffffu, tok, i + RADIUS);
        w[i] = __ldg(reinterpret_cast<const float4*>(W + (size_t)ct * EMB) + lane);
        msk[i] = (ct != 0) ? 1.0f : 0.0f;
    }

    float4 acc[C];
#pragma unroll
    for (int i = 0; i < C; i++)
        acc[i] = make_float4(-INFINITY, -INFINITY, -INFINITY, -INFINITY);

#pragma unroll
    for (int t = 0; t < T; t++) {
        const int tk = __shfl_sync(0xffffffffu, tok, t);
        const float4* base =
            reinterpret_cast<const float4*>(U + (size_t)tk * RS * EMB);
#pragma unroll
        for (int j = 0; j < RS; j++) {
            const int i = t - j;               // dest output; compile-time test
            if (i >= 0 && i < C) {
                const float4 u = __ldg(base + j * (EMB / 4) + lane);
                acc[i].x = fmaxf(acc[i].x, u.x * w[i].x);
                acc[i].y = fmaxf(acc[i].y, u.y * w[i].y);
                acc[i].z = fmaxf(acc[i].z, u.z * w[i].z);
                acc[i].w = fmaxf(acc[i].w, u.w * w[i].w);
            }
        }
    }

#pragma unroll
    for (int i = 0; i < C; i++) {
        float4 h;
        h.x = acc[i].x * msk[i];
        h.y = acc[i].y * msk[i];
        h.z = acc[i].z * msk[i];
        h.w = acc[i].w * msk[i];
        // write-once output: evict-first, keep U/W resident
        __stcs(reinterpret_cast<float4*>(out + (size_t)(b * LL + L0 + i) * EMB) + lane, h);
    }
}

extern "C" void kernel_launch(void* const* d_in, const int* in_sizes, int n_in,
                              void* d_out, int out_size) {
    const int*   seq32 = (const int*)d_in[0];
    const float* W     = (const float*)d_in[1];
    const float* U     = (const float*)d_in[2];
    float*       out   = (float*)d_out;

    const int threads = 256;                  // 8 warps/block
    const int blocks  = (NPOS / C) / 8;       // 4096 warps -> 512 blocks
    region_encoder_kernel<<<blocks, threads>>>(seq32, W, U, out);
}

// round 16
// speedup vs baseline: 1.1600x; 1.0175x over previous
#include <cuda_runtime.h>
#include <cstdint>

#define RADIUS 5
#define RS 11            // region size
#define EMB 128
#define BB 32
#define LL 512
#define NPOS (BB * LL)   // 16384
#define C 4              // outputs per warp
#define T (C + 2 * RADIUS) // tokens per warp = 14

// FINAL (round-8 architecture; measured 12.77-13.02us across runs = the
// path-independent LTS-cap floor).
// Model: warm timed loop moves ~108MB of L2-traversing traffic (92MB U rows,
// read exactly once per (position,j) by construction; 8MB W; 8MB out) through
// the LTS cap (~6300 B/cyc ~= 8.4 TB/s at NAT clocks) -> floor ~= 12.8us.
// Verified invariant to: occupancy (2x), per-warp MLP (3x), L2 evict policy,
// ALU reduction, cp.async.bulk single-shot & ring, and LDG+TMA hybrids
// (LTS cap is path-independent: LDG.cv == TMA).
//
// Token-contiguous formulation: warp owns outputs [L0, L0+4). Token at
// position p contributes row U[t_p*11 + j] to output l = p+5-j, so one
// token's needed rows are a consecutive run inside its contiguous 5632B U
// block (coarse DRAM granularity on cold caches; read-once when warm).
__global__ __launch_bounds__(256, 4) void region_encoder_kernel(
    const int* __restrict__ seq32,
    const float* __restrict__ W,
    const float* __restrict__ U,
    float* __restrict__ out)
{
    const int warp = blockIdx.x * 8 + (threadIdx.x >> 5);  // 4096 warps
    const int lane = threadIdx.x & 31;

    const int b  = warp >> 7;             // / (LL/C) = /128
    const int L0 = (warp & 127) * C;      // first output of this chunk

    // ---- dtype detection + token loads in flight together ----
    // Lanes 16..31 sample odd 32-bit words of seq: int64 layout => all zero;
    // int32 layout (tokens uniform in [0,50000)) => essentially never all zero.
    int det = 0;
    if (lane >= 16) det = seq32[((lane - 16) << 1) + 1];

    // Lanes 0..13 load tokens p = L0-5+lane (speculative int32 layout).
    const int p    = L0 - RADIUS + lane;
    const bool inb = (lane < T) && ((unsigned)p < (unsigned)LL);
    const int idx  = b * LL + p;
    int tok = inb ? __ldg(seq32 + idx) : 0;

    const unsigned ball = __ballot_sync(0xffffffffu, det != 0);
    if (ball == 0u) {
        tok = inb ? __ldg(seq32 + (idx << 1)) : 0;  // int64 layout (cold path)
    }

    // ---- preload the 4 W rows + masks (early independent LDG.128) ----
    float4 w[C];
    float  msk[C];
#pragma unroll
    for (int i = 0; i < C; i++) {
        const int ct = __shfl_sync(0xffffffffu, tok, i + RADIUS);
        w[i] = __ldg(reinterpret_cast<const float4*>(W + (size_t)ct * EMB) + lane);
        msk[i] = (ct != 0) ? 1.0f : 0.0f;
    }

    float4 acc[C];
#pragma unroll
    for (int i = 0; i < C; i++)
        acc[i] = make_float4(-INFINITY, -INFINITY, -INFINITY, -INFINITY);

#pragma unroll
    for (int t = 0; t < T; t++) {
        const int tk = __shfl_sync(0xffffffffu, tok, t);
        const float4* base =
            reinterpret_cast<const float4*>(U + (size_t)tk * RS * EMB);
#pragma unroll
        for (int j = 0; j < RS; j++) {
            const int i = t - j;               // dest output; compile-time test
            if (i >= 0 && i < C) {
                const float4 u = __ldg(base + j * (EMB / 4) + lane);
                acc[i].x = fmaxf(acc[i].x, u.x * w[i].x);
                acc[i].y = fmaxf(acc[i].y, u.y * w[i].y);
                acc[i].z = fmaxf(acc[i].z, u.z * w[i].z);
                acc[i].w = fmaxf(acc[i].w, u.w * w[i].w);
            }
        }
    }

#pragma unroll
    for (int i = 0; i < C; i++) {
        float4 h;
        h.x = acc[i].x * msk[i];
        h.y = acc[i].y * msk[i];
        h.z = acc[i].z * msk[i];
        h.w = acc[i].w * msk[i];
        // write-once output: evict-first, keep U/W resident
        __stcs(reinterpret_cast<float4*>(out + (size_t)(b * LL + L0 + i) * EMB) + lane, h);
    }
}

extern "C" void kernel_launch(void* const* d_in, const int* in_sizes, int n_in,
                              void* d_out, int out_size) {
    const int*   seq32 = (const int*)d_in[0];
    const float* W     = (const float*)d_in[1];
    const float* U     = (const float*)d_in[2];
    float*       out   = (float*)d_out;

    const int threads = 256;                  // 8 warps/block
    const int blocks  = (NPOS / C) / 8;       // 4096 warps -> 512 blocks
    region_encoder_kernel<<<blocks, threads>>>(seq32, W, U, out);
}

// round 17
// speedup vs baseline: 1.1629x; 1.0025x over previous
#include <cuda_runtime.h>
#include <cstdint>

#define RADIUS 5
#define RS 11            // region size
#define EMB 128
#define BB 32
#define LL 512
#define NPOS (BB * LL)   // 16384
#define C 2              // outputs per warp (one per half-warp)
#define T (C + 2 * RADIUS) // 12 window tokens per warp

// 256-bit gather variant: tests whether the 12.8us plateau is byte-capped
// (LTS B/cyc, path-independent -> flat) or request-slot-capped (L1tex queue
// entries per instruction -> win). Each half-warp covers one 512B row with
// 16 lanes x 32B via ld.global.nc.L2::evict_last.v8.b32 (the 256-bit form
// sm_103 ptxas certifies); instruction/request count per byte is halved vs
// the LDG.128 kernels, bytes and cache lines identical.
__device__ __forceinline__ void ldg256(const float* p, float* v) {
    uint32_t r0, r1, r2, r3, r4, r5, r6, r7;
    asm("ld.global.nc.L2::evict_last.v8.b32 {%0,%1,%2,%3,%4,%5,%6,%7}, [%8];"
        : "=r"(r0), "=r"(r1), "=r"(r2), "=r"(r3),
          "=r"(r4), "=r"(r5), "=r"(r6), "=r"(r7)
        : "l"(p));
    v[0] = __uint_as_float(r0); v[1] = __uint_as_float(r1);
    v[2] = __uint_as_float(r2); v[3] = __uint_as_float(r3);
    v[4] = __uint_as_float(r4); v[5] = __uint_as_float(r5);
    v[6] = __uint_as_float(r6); v[7] = __uint_as_float(r7);
}

__global__ __launch_bounds__(256, 4) void region_encoder_kernel(
    const int* __restrict__ seq32,
    const float* __restrict__ W,
    const float* __restrict__ U,
    float* __restrict__ out)
{
    const int warp = blockIdx.x * 8 + (threadIdx.x >> 5);  // 8192 warps
    const int lane = threadIdx.x & 31;
    const int h    = lane >> 4;           // half-warp id: output L0+h
    const int hl   = lane & 15;           // lane within half: bytes [hl*32, hl*32+32)

    const int b  = warp >> 8;             // / (LL/C) = /256
    const int L0 = (warp & 255) * C;      // first output of this pair

    // ---- dtype detection + token loads in flight together ----
    // Lanes 16..31 sample odd 32-bit words of seq: int64 layout => all zero;
    // int32 layout (tokens uniform in [0,50000)) => essentially never all zero.
    int det = 0;
    if (lane >= 16) det = seq32[((lane - 16) << 1) + 1];

    // Lanes 0..11 load window tokens p = L0-5+lane (speculative int32 layout).
    const int p    = L0 - RADIUS + lane;
    const bool inb = (lane < T) && ((unsigned)p < (unsigned)LL);
    const int idx  = b * LL + p;
    int tok = inb ? __ldg(seq32 + idx) : 0;

    const unsigned ball = __ballot_sync(0xffffffffu, det != 0);
    if (ball == 0u) {
        tok = inb ? __ldg(seq32 + (idx << 1)) : 0;  // int64 layout (cold path)
    }

    // ---- W row for this half's output: one 256-bit load ----
    const int ct = __shfl_sync(0xffffffffu, tok, h + RADIUS);
    float w[8];
    ldg256(W + (size_t)ct * EMB + hl * 8, w);
    const float m = (ct != 0) ? 1.0f : 0.0f;

    float acc[8];
#pragma unroll
    for (int e = 0; e < 8; e++) acc[e] = -INFINITY;

    // ---- 11 rows per output, each one 256-bit load per half-warp ----
#pragma unroll
    for (int j = 0; j < RS; j++) {
        const int tk = __shfl_sync(0xffffffffu, tok, h + j);  // token p = l-5+j
        float u[8];
        ldg256(U + ((size_t)tk * RS + j) * EMB + hl * 8, u);
#pragma unroll
        for (int e = 0; e < 8; e++)
            acc[e] = fmaxf(acc[e], u[e] * w[e]);
    }

    // ---- masked store: lane hl writes floats [hl*8, hl*8+8) of output L0+h ----
    float4 h0, h1;
    h0.x = acc[0] * m; h0.y = acc[1] * m; h0.z = acc[2] * m; h0.w = acc[3] * m;
    h1.x = acc[4] * m; h1.y = acc[5] * m; h1.z = acc[6] * m; h1.w = acc[7] * m;
    float* orow = out + (size_t)(b * LL + L0 + h) * EMB + hl * 8;
    __stcs(reinterpret_cast<float4*>(orow),     h0);
    __stcs(reinterpret_cast<float4*>(orow) + 1, h1);
}

extern "C" void kernel_launch(void* const* d_in, const int* in_sizes, int n_in,
                              void* d_out, int out_size) {
    const int*   seq32 = (const int*)d_in[0];
    const float* W     = (const float*)d_in[1];
    const float* U     = (const float*)d_in[2];
    float*       out   = (float*)d_out;

    const int threads = 256;                  // 8 warps/block
    const int blocks  = (NPOS / C) / 8;       // 8192 warps -> 1024 blocks
    region_encoder_kernel<<<blocks, threads>>>(seq32, W, U, out);
}